// round 10
// baseline (speedup 1.0000x reference)
#include <cuda_runtime.h>
#include <math.h>

#define B_DIM 128
#define N_DIM 1024
#define H_DIM 128
#define SK    128          // split-K factor for layer 1
#define KC    (N_DIM / SK) // 8: K-chunk per CTA

// Scratch (allocation-free rule: device globals).
__device__ float g_c[B_DIM * N_DIM];                    // 512 KB correlation output
__device__ float g_part[SK * B_DIM * H_DIM];            // 8 MB layer-1 partials

__device__ __forceinline__ float celu1(float v) {
    return v > 0.f ? v : expm1f(v);
}

// Bank-conflict swizzle for FFT arrays (stride-33 rows).
#define SWZ(j) ((j) + ((j) >> 5))
#define FFT_LEN 1056   // SWZ(1023) = 1054

__device__ __forceinline__ float2 cmul(float2 a, float2 b) {
    return make_float2(a.x * b.x - a.y * b.y, a.x * b.y + a.y * b.x);
}
__device__ __forceinline__ float2 cadd(float2 a, float2 b) {
    return make_float2(a.x + b.x, a.y + b.y);
}
__device__ __forceinline__ float2 csub(float2 a, float2 b) {
    return make_float2(a.x - b.x, a.y - b.y);
}

// ============================================================================
// Radix-4 Stockham DIF stage (S = 1,4,16,64,256), 256 butterflies, one per
// local thread id t in [0,256). NO internal sync — caller barriers.
// ============================================================================
template <int S>
__device__ __forceinline__ void r4stage(const float2* __restrict__ in,
                                        float2* __restrict__ out,
                                        const float2* __restrict__ tw,
                                        int t) {
    const int q  = t & (S - 1);
    const int pS = t - q;                  // p*S, in [0,256)

    float2 a0 = in[SWZ(t)];
    float2 a1 = in[SWZ(t + 256)];
    float2 a2 = in[SWZ(t + 512)];
    float2 a3 = in[SWZ(t + 768)];

    float2 w1 = tw[pS];
    float2 w2 = cmul(w1, w1);
    float2 w3 = cmul(w2, w1);

    float2 s02 = cadd(a0, a2), d02 = csub(a0, a2);
    float2 s13 = cadd(a1, a3), d13 = csub(a1, a3);

    float2 b0 = cadd(s02, s13);
    float2 b2 = csub(s02, s13);
    float2 mi = make_float2(d13.y, -d13.x);      // -i * d13
    float2 b1 = cadd(d02, mi);
    float2 b3 = csub(d02, mi);

    const int o = 4 * pS + q;
    out[SWZ(o)]         = b0;
    out[SWZ(o + S)]     = cmul(b1, w1);
    out[SWZ(o + 2 * S)] = cmul(b2, w2);
    out[SWZ(o + 3 * S)] = cmul(b3, w3);
}

// ============================================================================
// Kernel 1: circular autocorrelation per batch via FFT, two thread-teams.
//   c[b,p] = (1/N) IDFT( sum_d |DFT(x_d)|^2 )[p];  S real+even => IDFT == DFT
// Phase 1 (teams in parallel):  team0: FFT(z = x0 + i*x1)   team1: FFT(x2)
// Glue:  S[k] = (|Z[k]|^2+|Z[N-k]|^2)/2 + |X2[k]|^2  -> FFT#3 input
// Phase 2 (team0 only): FFT(S);  c[p] = Re(.)/N^2
// 512 threads = 16 warps; 10 serial FFT stages total per batch.
// ============================================================================
__global__ __launch_bounds__(512) void corr_fft_kernel(const float* __restrict__ x) {
    __shared__ __align__(16) float2 buf[4][FFT_LEN];   // team0: 0/1, team1: 2/3 (~33KB)
    __shared__ __align__(16) float2 tw[256];

    const int b   = blockIdx.x;
    const int tid = threadIdx.x;
    const int t   = tid & 255;
    const int team = tid >> 8;
    const float* xb = x + (size_t)b * N_DIM * 3;

    // tw[j] = exp(-2*pi*i*j/1024), j < 256
    if (tid < 256) {
        float sv, cv;
        sincospif((float)tid * (1.0f / 512.0f), &sv, &cv);
        tw[tid] = make_float2(cv, -sv);
    }
    // Inputs: team0's A = x0 + i*x1 ; team1's A = x2 + 0i
    for (int q = tid; q < N_DIM; q += 512) {
        float v0 = xb[3 * q + 0];
        float v1 = xb[3 * q + 1];
        float v2 = xb[3 * q + 2];
        buf[0][SWZ(q)] = make_float2(v0, v1);
        buf[2][SWZ(q)] = make_float2(v2, 0.f);
    }
    __syncthreads();

    // Phase 1: both teams, 5 stages (A=buf[2*team], B=buf[2*team+1])
    {
        float2* A = buf[2 * team];
        float2* B = buf[2 * team + 1];
        r4stage<1>(A, B, tw, t);    __syncthreads();
        r4stage<4>(B, A, tw, t);    __syncthreads();
        r4stage<16>(A, B, tw, t);   __syncthreads();
        r4stage<64>(B, A, tw, t);   __syncthreads();
        r4stage<256>(A, B, tw, t);  __syncthreads();
    }
    // Z in buf[1], X2 in buf[3]

    // Glue: build FFT#3 input in buf[0]
    for (int k = tid; k < N_DIM; k += 512) {
        float2 a = buf[1][SWZ(k)];
        float2 c = buf[1][SWZ((N_DIM - k) & (N_DIM - 1))];
        float2 e = buf[3][SWZ(k)];
        float s = 0.5f * (a.x * a.x + a.y * a.y + c.x * c.x + c.y * c.y)
                + (e.x * e.x + e.y * e.y);
        buf[0][SWZ(k)] = make_float2(s, 0.f);
    }
    __syncthreads();

    // Phase 2: FFT#3 on team0 only (barriers outside the guard)
    if (tid < 256) r4stage<1>(buf[0], buf[1], tw, t);    __syncthreads();
    if (tid < 256) r4stage<4>(buf[1], buf[0], tw, t);    __syncthreads();
    if (tid < 256) r4stage<16>(buf[0], buf[1], tw, t);   __syncthreads();
    if (tid < 256) r4stage<64>(buf[1], buf[0], tw, t);   __syncthreads();
    if (tid < 256) r4stage<256>(buf[0], buf[1], tw, t);  __syncthreads();

    const float inv = 1.0f / ((float)N_DIM * (float)N_DIM);
    float* cb = g_c + (size_t)b * N_DIM;
    for (int p = tid; p < N_DIM; p += 512)
        cb[p] = buf[1][SWZ(p)].x * inv;
}

// ============================================================================
// Kernel 2: layer 1 as split-K GEMM.  C[128,1024] @ W1[1024,128].
// ============================================================================
__global__ __launch_bounds__(256) void l1_kernel(const float* __restrict__ W1) {
    __shared__ __align__(16) float ct[KC][B_DIM];   // c^T chunk: [kk][m]
    __shared__ __align__(16) float wt[KC][H_DIM];   // W1 chunk:  [kk][n]

    const int sk = blockIdx.x;
    const int k0 = sk * KC;
    const int t  = threadIdx.x;

    {
        int m = t >> 1, h = t & 1;
        float4 v = *(const float4*)&g_c[(size_t)m * N_DIM + k0 + 4 * h];
        ct[4 * h + 0][m] = v.x;
        ct[4 * h + 1][m] = v.y;
        ct[4 * h + 2][m] = v.z;
        ct[4 * h + 3][m] = v.w;
    }
    {
        int kk = t >> 5, q = t & 31;
        *(float4*)&wt[kk][4 * q] =
            *(const float4*)&W1[(size_t)(k0 + kk) * H_DIM + 4 * q];
    }
    __syncthreads();

    const int m0 = (t >> 4) * 8;
    const int n0 = (t & 15) * 8;

    float4 acc[8][2];
#pragma unroll
    for (int i = 0; i < 8; i++) {
        acc[i][0] = make_float4(0.f, 0.f, 0.f, 0.f);
        acc[i][1] = make_float4(0.f, 0.f, 0.f, 0.f);
    }

#pragma unroll
    for (int kk = 0; kk < KC; kk++) {
        float4 aA = *(const float4*)&ct[kk][m0];
        float4 aB = *(const float4*)&ct[kk][m0 + 4];
        float4 b0 = *(const float4*)&wt[kk][n0];
        float4 b1 = *(const float4*)&wt[kk][n0 + 4];
        float a[8] = {aA.x, aA.y, aA.z, aA.w, aB.x, aB.y, aB.z, aB.w};
#pragma unroll
        for (int i = 0; i < 8; i++) {
            acc[i][0].x = fmaf(a[i], b0.x, acc[i][0].x);
            acc[i][0].y = fmaf(a[i], b0.y, acc[i][0].y);
            acc[i][0].z = fmaf(a[i], b0.z, acc[i][0].z);
            acc[i][0].w = fmaf(a[i], b0.w, acc[i][0].w);
            acc[i][1].x = fmaf(a[i], b1.x, acc[i][1].x);
            acc[i][1].y = fmaf(a[i], b1.y, acc[i][1].y);
            acc[i][1].z = fmaf(a[i], b1.z, acc[i][1].z);
            acc[i][1].w = fmaf(a[i], b1.w, acc[i][1].w);
        }
    }

    float* dst = g_part + (size_t)sk * B_DIM * H_DIM;
#pragma unroll
    for (int i = 0; i < 8; i++) {
        *(float4*)&dst[(size_t)(m0 + i) * H_DIM + n0]     = acc[i][0];
        *(float4*)&dst[(size_t)(m0 + i) * H_DIM + n0 + 4] = acc[i][1];
    }
}

// ============================================================================
// Kernel 3: per-batch tail (reduce partials, celu, layer2, celu, layer3).
// ============================================================================
__global__ __launch_bounds__(256) void mlp_tail_kernel(
    const float* __restrict__ b1, const float* __restrict__ W2,
    const float* __restrict__ b2, const float* __restrict__ W3,
    const float* __restrict__ b3, float* __restrict__ y)
{
    __shared__ float h1s[H_DIM];
    __shared__ float red[256];
    __shared__ float rsum[4];

    const int m = blockIdx.x;
    const int t = threadIdx.x;
    const int j    = t & 127;
    const int half = t >> 7;

    float s = 0.f;
    {
        const float* base = g_part + (size_t)half * 64 * (B_DIM * H_DIM)
                                   + (size_t)m * H_DIM + j;
#pragma unroll 16
        for (int sk = 0; sk < 64; sk++)
            s += base[(size_t)sk * (B_DIM * H_DIM)];
    }
    red[t] = s;
    __syncthreads();
    if (half == 0)
        h1s[j] = celu1(red[j] + red[j + 128] + b1[j]);
    __syncthreads();

    float a = 0.f;
    {
        const float* w = W2 + (size_t)half * 64 * H_DIM + j;
        const float* h = h1s + half * 64;
#pragma unroll 16
        for (int k = 0; k < 64; k++)
            a = fmaf(h[k], w[(size_t)k * H_DIM], a);
    }
    __syncthreads();
    red[t] = a;
    __syncthreads();

    float v = 0.f;
    if (half == 0) {
        float h2 = celu1(red[j] + red[j + 128] + b2[j]);
        v = h2 * W3[j];
#pragma unroll
        for (int off = 16; off; off >>= 1)
            v += __shfl_xor_sync(0xffffffffu, v, off);
        if ((j & 31) == 0) rsum[j >> 5] = v;
    }
    __syncthreads();
    if (t == 0)
        y[m] = rsum[0] + rsum[1] + rsum[2] + rsum[3] + b3[0];
}

extern "C" void kernel_launch(void* const* d_in, const int* in_sizes, int n_in,
                              void* d_out, int out_size) {
    const float* x  = (const float*)d_in[0];
    const float* W1 = (const float*)d_in[1];
    const float* b1 = (const float*)d_in[2];
    const float* W2 = (const float*)d_in[3];
    const float* b2 = (const float*)d_in[4];
    const float* W3 = (const float*)d_in[5];
    const float* b3 = (const float*)d_in[6];
    float* y = (float*)d_out;

    corr_fft_kernel<<<B_DIM, 512>>>(x);
    l1_kernel<<<SK, 256>>>(W1);
    mlp_tail_kernel<<<B_DIM, 256>>>(b1, W2, b2, W3, b3, y);
}